// round 11
// baseline (speedup 1.0000x reference)
#include <cuda_runtime.h>

#define BS     4096
#define SEGLEN 8192
#define LAM1   8e-05f
#define LAM2   8e-05f
#define TPB    256
#define NWARP  (TPB / 32)
#define GRID   888   // 148 SMs x occ 6 -> single persistent wave

// Scratch (allocation-free rule: __device__ globals).
// g_hist is zero at load; finalize re-zeros it after use (replay-safe).
__device__ float g_base[BS];     // LAM1*smooth + LAM2*spars per row
__device__ int   g_ms[BS];       // argmax index per row
__device__ int   g_hist[SEGLEN]; // histogram of ms over negative rows

// ---------------------------------------------------------------------------
// Kernel 1 (persistent): grid-stride over rows; per row: coalesced
// interleaved float4 loads, float4-granularity argmax, boundary __ldg.
// ---------------------------------------------------------------------------
__global__ __launch_bounds__(TPB) void row_stats(const float* __restrict__ scores,
                                                 const int*   __restrict__ labels) {
    const int t = threadIdx.x, lane = t & 31, w = t >> 5;
    __shared__ float ssum[NWARP], ssq[NWARP], smax[NWARP];
    __shared__ int   sidx[NWARP];

    for (int row = blockIdx.x; row < BS; row += GRID) {
        const float*  rf = scores + (size_t)row * SEGLEN;
        const float4* rp = (const float4*)rf;

        float sum = 0.f, sq = 0.f, maxv = -1.f;
        int maxq = 0;  // float4-granularity index of running max

#pragma unroll
        for (int g = 0; g < 8; g++) {
            const int v4 = g * TPB + t;     // coalesced across lanes
            const int e  = v4 * 4;
            float4 x = rp[v4];
            float nxt = (e + 4 < SEGLEN) ? __ldg(rf + e + 4) : x.w;  // last: diff 0

            sum += (x.x + x.y) + (x.z + x.w);
            float d0 = x.y - x.x, d1 = x.z - x.y, d2 = x.w - x.z, d3 = nxt - x.w;
            sq += d0 * d0 + d1 * d1 + d2 * d2 + d3 * d3;

            // strict > keeps earliest v4 within thread (v4 ascends with g)
            float m4 = fmaxf(fmaxf(x.x, x.y), fmaxf(x.z, x.w));
            if (m4 > maxv) { maxv = m4; maxq = v4; }
        }

        // warp reduce (fixed order -> deterministic); tie -> min v4 index
#pragma unroll
        for (int off = 16; off > 0; off >>= 1) {
            sum += __shfl_down_sync(0xFFFFFFFFu, sum, off);
            sq  += __shfl_down_sync(0xFFFFFFFFu, sq,  off);
            float ov = __shfl_down_sync(0xFFFFFFFFu, maxv, off);
            int   oq = __shfl_down_sync(0xFFFFFFFFu, maxq, off);
            if (ov > maxv || (ov == maxv && oq < maxq)) { maxv = ov; maxq = oq; }
        }
        if (lane == 0) { ssum[w] = sum; ssq[w] = sq; smax[w] = maxv; sidx[w] = maxq; }
        __syncthreads();

        if (t == 0) {
            float S = 0.f, Q = 0.f, M = -1.f;
            int Qi = 0;
#pragma unroll
            for (int i = 0; i < NWARP; i++) {
                S += ssum[i];
                Q += ssq[i];
                if (smax[i] > M || (smax[i] == M && sidx[i] < Qi)) { M = smax[i]; Qi = sidx[i]; }
            }
            // resolve first occurrence inside the earliest winning float4 (L2-hot)
            float4 xx = rp[Qi];
            int e = Qi * 4;
            int idx = (xx.x == M) ? e : (xx.y == M) ? e + 1 : (xx.z == M) ? e + 2 : e + 3;
            g_base[row] = LAM1 * Q + LAM2 * S;
            g_ms[row]   = idx;
            if (labels[row] == 0) atomicAdd(&g_hist[idx], 1);  // int -> deterministic
        }
        __syncthreads();  // protect shared arrays before next row iteration
    }
    cudaTriggerProgrammaticLaunchCompletion();
}

// ---------------------------------------------------------------------------
// Kernel 2 (single block, 1024 threads, PDL):
//   T[m] = S1[m] - m*S0[m] via one fused suffix scan of (S0, S1).
//   Gather margin = T[ms[i]] for positive rows + deterministic reduction.
//   Self-cleans g_hist for the next graph replay.
// ---------------------------------------------------------------------------
__global__ __launch_bounds__(1024) void finalize(const int* __restrict__ labels,
                                                 float* __restrict__ out) {
    __shared__ int   Tm[SEGLEN];    // T[m]
    __shared__ int   wt0[32], wt1[32], wo0[32], wo1[32];
    __shared__ float red[32];

    const int t = threadIdx.x;
    const int lane = t & 31, w = t >> 5;
    const int base = t * 8;         // this thread owns bins [8t, 8t+8)

    // ---- prologue: independent of row_stats ----
    int4 lb = ((const int4*)labels)[t];   // rows 4t..4t+3
    // ---- wait for row_stats results ----
    cudaGridDependencySynchronize();

    // load this thread's 8 hist bins (coalesced int4, L2-hot)
    int4 h0 = ((const int4*)g_hist)[2 * t];
    int4 h1 = ((const int4*)g_hist)[2 * t + 1];
    int4   ms = ((const int4*)g_ms)[t];
    float4 gb = ((const float4*)g_base)[t];

    int hreg[8] = {h0.x, h0.y, h0.z, h0.w, h1.x, h1.y, h1.z, h1.w};

    // chunk totals: c0 = sum h, c1 = sum h*(bin+1)
    int c0 = 0, c1 = 0;
#pragma unroll
    for (int k = 0; k < 8; k++) { c0 += hreg[k]; c1 += hreg[k] * (base + k + 1); }

    // warp inclusive suffix scan of (c0, c1)
    int i0 = c0, i1 = c1;
#pragma unroll
    for (int off = 1; off < 32; off <<= 1) {
        int v0 = __shfl_down_sync(0xFFFFFFFFu, i0, off);
        int v1 = __shfl_down_sync(0xFFFFFFFFu, i1, off);
        if (lane + off < 32) { i0 += v0; i1 += v1; }
    }
    if (lane == 0) { wt0[w] = i0; wt1[w] = i1; }
    __syncthreads();

    // warp 0: exclusive suffix over 32 warp totals (both components)
    if (w == 0) {
        int v0 = wt0[lane], v1 = wt1[lane];
        int s0 = v0, s1 = v1;
#pragma unroll
        for (int off = 1; off < 32; off <<= 1) {
            int u0 = __shfl_down_sync(0xFFFFFFFFu, s0, off);
            int u1 = __shfl_down_sync(0xFFFFFFFFu, s1, off);
            if (lane + off < 32) { s0 += u0; s1 += u1; }
        }
        wo0[lane] = s0 - v0;  // sum of warps strictly after lane
        wo1[lane] = s1 - v1;
    }
    __syncthreads();

    // serial descending within chunk: inclusive suffixes r0, r1; write T
    int r0 = (i0 - c0) + wo0[w];
    int r1 = (i1 - c1) + wo1[w];
#pragma unroll
    for (int k = 7; k >= 0; k--) {
        const int bin = base + k;
        r0 += hreg[k];
        r1 += hreg[k] * (bin + 1);
        Tm[bin] = r1 - bin * r0;
    }
    __syncthreads();

    // per-positive-row loss (this thread's 4 rows), fixed order
    float acc = 0.f;
    if (lb.x == 1) acc += gb.x + (float)Tm[ms.x];
    if (lb.y == 1) acc += gb.y + (float)Tm[ms.y];
    if (lb.z == 1) acc += gb.z + (float)Tm[ms.z];
    if (lb.w == 1) acc += gb.w + (float)Tm[ms.w];

    // self-clean histogram for the next graph replay
    ((int4*)g_hist)[2 * t]     = make_int4(0, 0, 0, 0);
    ((int4*)g_hist)[2 * t + 1] = make_int4(0, 0, 0, 0);

    // deterministic tree reduction
#pragma unroll
    for (int off = 16; off > 0; off >>= 1)
        acc += __shfl_down_sync(0xFFFFFFFFu, acc, off);
    if (lane == 0) red[w] = acc;
    __syncthreads();
    if (w == 0) {
        float v = red[lane];
#pragma unroll
        for (int off = 16; off > 0; off >>= 1)
            v += __shfl_down_sync(0xFFFFFFFFu, v, off);
        if (lane == 0) out[0] = v / (float)BS;
    }
}

extern "C" void kernel_launch(void* const* d_in, const int* in_sizes, int n_in,
                              void* d_out, int out_size) {
    const float* scores = (const float*)d_in[0];
    const int*   labels = (const int*)d_in[1];
    float*       out    = (float*)d_out;

    row_stats<<<GRID, TPB>>>(scores, labels);

    // finalize with Programmatic Dependent Launch
    cudaLaunchConfig_t cfg = {};
    cfg.gridDim  = dim3(1, 1, 1);
    cfg.blockDim = dim3(1024, 1, 1);
    cfg.dynamicSmemBytes = 0;
    cudaLaunchAttribute attrs[1];
    attrs[0].id = cudaLaunchAttributeProgrammaticStreamSerialization;
    attrs[0].val.programmaticStreamSerializationAllowed = 1;
    cfg.attrs = attrs;
    cfg.numAttrs = 1;
    cudaLaunchKernelEx(&cfg, finalize, labels, out);
}